// round 1
// baseline (speedup 1.0000x reference)
#include <cuda_runtime.h>
#include <cuda_bf16.h>
#include <cstdint>
#include <cstddef>

// Problem constants
#define NB 16
#define NT 1024
#define ND 256
// DS = 4

// Tile config
#define BM 128
#define BN 128
#define LDSX 264   // bf16 elements per smem row (264*2 = 528B = 33*16B, odd 16B stride -> conflict-free ldmatrix)
#define SMEM_BYTES (2 * 128 * LDSX * 2)

// Scratch (no allocations allowed -> __device__ globals)
__device__ __align__(16) __nv_bfloat16 g_zbf[NB * NT * ND];  // 8.4 MB
__device__ float  g_z2[NB * NT];
__device__ double g_partial[1024];

// ---------------------------------------------------------------------------
// Kernel 0: z -> bf16 copy + per-row sum of squares (z2)
// grid = NB*NT/8 blocks, 256 threads (one warp per row)
// ---------------------------------------------------------------------------
__global__ void prep_kernel(const float* __restrict__ z) {
    const int row  = blockIdx.x * 8 + (threadIdx.x >> 5);
    const int lane = threadIdx.x & 31;

    const float4* zr = reinterpret_cast<const float4*>(z) + (size_t)row * (ND / 4);
    float4 v0 = zr[lane];        // cols 4*lane   .. 4*lane+3
    float4 v1 = zr[lane + 32];   // cols 128+4*lane ..

    float ss = v0.x * v0.x + v0.y * v0.y + v0.z * v0.z + v0.w * v0.w
             + v1.x * v1.x + v1.y * v1.y + v1.z * v1.z + v1.w * v1.w;
    #pragma unroll
    for (int o = 16; o; o >>= 1) ss += __shfl_xor_sync(0xffffffffu, ss, o);
    if (lane == 0) g_z2[row] = ss;

    uint2* dst = reinterpret_cast<uint2*>(g_zbf + (size_t)row * ND);
    __nv_bfloat162 a0 = __floats2bfloat162_rn(v0.x, v0.y);
    __nv_bfloat162 a1 = __floats2bfloat162_rn(v0.z, v0.w);
    __nv_bfloat162 b0 = __floats2bfloat162_rn(v1.x, v1.y);
    __nv_bfloat162 b1 = __floats2bfloat162_rn(v1.z, v1.w);
    uint2 p0, p1;
    p0.x = *reinterpret_cast<uint32_t*>(&a0);
    p0.y = *reinterpret_cast<uint32_t*>(&a1);
    p1.x = *reinterpret_cast<uint32_t*>(&b0);
    p1.y = *reinterpret_cast<uint32_t*>(&b1);
    dst[lane]      = p0;
    dst[lane + 32] = p1;
}

// ---------------------------------------------------------------------------
// Main fused kernel: per (b, t-tile, s-tile):
//   Phase A: G = Zt * Zs^T  (128x128x256 bf16 via mma.sync m16n8k16)
//   Phase B: stream gt_dT tile, w = expf(sum g^2 / (2 sigma^2)),
//            partial += w * (z2[t] - G[t,s])
// grid = (8, 8, 16), 256 threads
// ---------------------------------------------------------------------------
#define LDSM4(r0, r1, r2, r3, addr)                                              \
    asm volatile("ldmatrix.sync.aligned.m8n8.x4.shared.b16 {%0,%1,%2,%3}, [%4];" \
                 : "=r"(r0), "=r"(r1), "=r"(r2), "=r"(r3) : "r"(addr))

#define MMA16816(d, a, b0r, b1r)                                                 \
    asm volatile("mma.sync.aligned.m16n8k16.row.col.f32.bf16.bf16.f32 "          \
                 "{%0,%1,%2,%3}, {%4,%5,%6,%7}, {%8,%9}, {%0,%1,%2,%3};"         \
                 : "+f"(d[0]), "+f"(d[1]), "+f"(d[2]), "+f"(d[3])                \
                 : "r"(a[0]), "r"(a[1]), "r"(a[2]), "r"(a[3]), "r"(b0r), "r"(b1r))

__global__ void __launch_bounds__(256, 1)
main_kernel(const float* __restrict__ gt, const float* __restrict__ sigma) {
    extern __shared__ __align__(16) __nv_bfloat16 sm[];
    __nv_bfloat16* As = sm;
    __nv_bfloat16* Bs = sm + 128 * LDSX;

    const int bb = blockIdx.z;
    const int t0 = blockIdx.y * BM;
    const int sB = blockIdx.x * BN;
    const int tid = threadIdx.x;

    // ---- load Zt / Zs tiles into smem (bf16, padded stride) ----
    {
        const int4* gzt = reinterpret_cast<const int4*>(g_zbf + ((size_t)bb * NT + t0) * ND);
        const int4* gzs = reinterpret_cast<const int4*>(g_zbf + ((size_t)bb * NT + sB) * ND);
        #pragma unroll
        for (int i = 0; i < 16; i++) {
            int idx = tid + i * 256;           // 0..4095 : 128 rows x 32 int4
            int r = idx >> 5, c = idx & 31;
            *reinterpret_cast<int4*>(As + r * LDSX + c * 8) = gzt[idx];
            *reinterpret_cast<int4*>(Bs + r * LDSX + c * 8) = gzs[idx];
        }
    }
    __syncthreads();

    const int lane = tid & 31;
    const int wid  = tid >> 5;
    const int wm = (wid >> 1) * 32;  // warp row offset: 0,32,64,96
    const int wn = (wid & 1) * 64;   // warp col offset: 0,64

    float acc[2][8][4];
    #pragma unroll
    for (int mi = 0; mi < 2; mi++)
        #pragma unroll
        for (int ni = 0; ni < 8; ni++)
            #pragma unroll
            for (int r = 0; r < 4; r++) acc[mi][ni][r] = 0.f;

    const uint32_t aBase = (uint32_t)__cvta_generic_to_shared(As);
    const uint32_t bBase = (uint32_t)__cvta_generic_to_shared(Bs);

    // A ldmatrix.x4: lanes 0-15 -> rows (wm+mi*16 + lane&15) @ k-lo, lanes 16-31 same rows @ k-hi
    const uint32_t aAddr0 = aBase + (((wm + (lane & 15)) * LDSX + (lane >> 4) * 8)) * 2;
    // B ldmatrix.x4: row = wn + nj*16 + (lane&7) + 8*(lane>>4); kcol = ((lane>>3)&1)*8
    const uint32_t bAddr0 = bBase + (((wn + (lane & 7) + ((lane >> 4) << 3)) * LDSX
                                     + ((lane >> 3) & 1) * 8)) * 2;

    #pragma unroll
    for (int kk = 0; kk < 16; kk++) {
        uint32_t a[2][4];
        #pragma unroll
        for (int mi = 0; mi < 2; mi++) {
            uint32_t addr = aAddr0 + (uint32_t)(mi * 16 * LDSX * 2) + (uint32_t)(kk * 32);
            LDSM4(a[mi][0], a[mi][1], a[mi][2], a[mi][3], addr);
        }
        uint32_t bf[8][2];
        #pragma unroll
        for (int nj = 0; nj < 4; nj++) {
            uint32_t addr = bAddr0 + (uint32_t)(nj * 16 * LDSX * 2) + (uint32_t)(kk * 32);
            uint32_t r0, r1, r2, r3;
            LDSM4(r0, r1, r2, r3, addr);
            bf[2 * nj][0] = r0; bf[2 * nj][1] = r1;
            bf[2 * nj + 1][0] = r2; bf[2 * nj + 1][1] = r3;
        }
        #pragma unroll
        for (int mi = 0; mi < 2; mi++)
            #pragma unroll
            for (int ni = 0; ni < 8; ni++)
                MMA16816(acc[mi][ni], a[mi], bf[ni][0], bf[ni][1]);
    }

    // ---- Phase B: stream gt, fuse w + reduction ----
    float sg0 = sigma[0], sg1 = sigma[1], sg2 = sigma[2], sg3 = sigma[3];
    const float inv0 = 1.0f / (2.0f * sg0 * sg0);
    const float inv1 = 1.0f / (2.0f * sg1 * sg1);
    const float inv2 = 1.0f / (2.0f * sg2 * sg2);
    const float inv3 = 1.0f / (2.0f * sg3 * sg3);

    const int rowc = lane >> 2;          // 0..7
    const int colc = (lane & 3) * 2;     // 0,2,4,6

    float z2v[2][2];
    #pragma unroll
    for (int mi = 0; mi < 2; mi++)
        #pragma unroll
        for (int h = 0; h < 2; h++)
            z2v[mi][h] = g_z2[bb * NT + t0 + wm + mi * 16 + rowc + h * 8];

    float part = 0.f;
    #pragma unroll
    for (int mi = 0; mi < 2; mi++) {
        #pragma unroll
        for (int h = 0; h < 2; h++) {
            const int t = t0 + wm + mi * 16 + rowc + h * 8;
            // gt float4 index for element (b,t,s) is exactly (b*NT+t)*NT + s
            const float4* gp = reinterpret_cast<const float4*>(gt)
                             + ((size_t)bb * NT + t) * NT + (sB + wn + colc);
            const float zz = z2v[mi][h];
            #pragma unroll
            for (int ni = 0; ni < 8; ni++) {
                float4 gA = gp[ni * 8];      // (t, s)
                float4 gB = gp[ni * 8 + 1];  // (t, s+1)
                float q0 = gA.x * gA.x * inv0 + gA.y * gA.y * inv1
                         + gA.z * gA.z * inv2 + gA.w * gA.w * inv3;
                float q1 = gB.x * gB.x * inv0 + gB.y * gB.y * inv1
                         + gB.z * gB.z * inv2 + gB.w * gB.w * inv3;
                float w0 = __expf(q0);
                float w1 = __expf(q1);
                part += w0 * (zz - acc[mi][ni][h * 2 + 0]);
                part += w1 * (zz - acc[mi][ni][h * 2 + 1]);
            }
        }
    }

    // ---- CTA reduction (deterministic), one partial per CTA ----
    #pragma unroll
    for (int o = 16; o; o >>= 1) part += __shfl_xor_sync(0xffffffffu, part, o);
    __syncthreads();  // smem no longer needed for tiles
    double* red = reinterpret_cast<double*>(sm);
    if (lane == 0) red[wid] = (double)part;
    __syncthreads();
    if (tid == 0) {
        double ssum = 0.0;
        #pragma unroll
        for (int i = 0; i < 8; i++) ssum += red[i];
        g_partial[blockIdx.z * 64 + blockIdx.y * 8 + blockIdx.x] = ssum;
    }
}

// ---------------------------------------------------------------------------
// Finalize: fixed-order tree reduction of 1024 partials -> scalar loss
// ---------------------------------------------------------------------------
__global__ void finalize_kernel(float* __restrict__ out) {
    __shared__ double red[256];
    double v = 0.0;
    for (int i = threadIdx.x; i < 1024; i += 256) v += g_partial[i];
    red[threadIdx.x] = v;
    __syncthreads();
    for (int off = 128; off; off >>= 1) {
        if (threadIdx.x < off) red[threadIdx.x] += red[threadIdx.x + off];
        __syncthreads();
    }
    if (threadIdx.x == 0)
        out[0] = (float)(red[0] * (2.0 / ((double)NB * (double)NT * (double)NT)));
}

// ---------------------------------------------------------------------------
extern "C" void kernel_launch(void* const* d_in, const int* in_sizes, int n_in,
                              void* d_out, int out_size) {
    const float* z     = (const float*)d_in[0];  // [16,1024,256]
    const float* gt    = (const float*)d_in[1];  // [16,1024,1024,4]
    const float* sigma = (const float*)d_in[2];  // [4]
    float* out = (float*)d_out;

    cudaFuncSetAttribute(main_kernel, cudaFuncAttributeMaxDynamicSharedMemorySize, SMEM_BYTES);

    prep_kernel<<<NB * NT / 8, 256>>>(z);
    main_kernel<<<dim3(8, 8, NB), 256, SMEM_BYTES>>>(gt, sigma);
    finalize_kernel<<<1, 256>>>(out);
}